// round 1
// baseline (speedup 1.0000x reference)
#include <cuda_runtime.h>

#define NNODES 100000
#define EEDGES 1600000
#define HID    128
#define NCLS   40

// ---------------- scratch (device globals; no allocation allowed) ------------
__device__ __align__(128) float g_h1[NNODES * HID];
__device__ __align__(128) float g_h2[NNODES * HID];
__device__ __align__(128) float g_agg[NNODES * HID];
__device__ int   g_outdeg[NNODES];
__device__ int   g_indeg[NNODES];
__device__ int   g_cursor[NNODES];
__device__ float g_onorm[NNODES];
__device__ float g_inorm[NNODES];
__device__ int   g_rowoff[NNODES + 1];
__device__ int   g_bsums[256];
__device__ int   g_esrc[EEDGES];

// ---------------- small prep kernels ----------------------------------------
__global__ void zero_ints_kernel(int n) {
    int i = blockIdx.x * blockDim.x + threadIdx.x;
    if (i < n) { g_outdeg[i] = 0; g_indeg[i] = 0; g_cursor[i] = 0; }
}

__global__ void degree_kernel(const int* __restrict__ src,
                              const int* __restrict__ dst, int E) {
    int e = blockIdx.x * blockDim.x + threadIdx.x;
    if (e < E) {
        atomicAdd(&g_outdeg[src[e]], 1);
        atomicAdd(&g_indeg[dst[e]], 1);
    }
}

__global__ void norm_kernel(int n) {
    int i = blockIdx.x * blockDim.x + threadIdx.x;
    if (i < n) {
        g_onorm[i] = rsqrtf((float)max(g_outdeg[i], 1));
        g_inorm[i] = rsqrtf((float)max(g_indeg[i], 1));
    }
}

// exclusive scan of g_indeg -> g_rowoff (3 phases)
__global__ void scan1_kernel(int n) {
    __shared__ int s[1024];
    int tid = threadIdx.x;
    int i = blockIdx.x * 1024 + tid;
    int v = (i < n) ? g_indeg[i] : 0;
    s[tid] = v;
    __syncthreads();
    #pragma unroll
    for (int off = 1; off < 1024; off <<= 1) {
        int t = 0;
        if (tid >= off) t = s[tid - off];
        __syncthreads();
        s[tid] += t;
        __syncthreads();
    }
    if (i < n) g_rowoff[i] = s[tid] - v;   // exclusive (block-local)
    if (tid == 1023) g_bsums[blockIdx.x] = s[1023];
}

__global__ void scan2_kernel(int nb, int n, int E) {
    if (threadIdx.x == 0 && blockIdx.x == 0) {
        int run = 0;
        for (int b = 0; b < nb; b++) { int t = g_bsums[b]; g_bsums[b] = run; run += t; }
        g_rowoff[n] = E;
    }
}

__global__ void scan3_kernel(int n) {
    int i = blockIdx.x * 1024 + threadIdx.x;
    if (i < n) g_rowoff[i] += g_bsums[blockIdx.x];
}

__global__ void fill_kernel(const int* __restrict__ src,
                            const int* __restrict__ dst, int E) {
    int e = blockIdx.x * blockDim.x + threadIdx.x;
    if (e < E) {
        int d = dst[e];
        int pos = g_rowoff[d] + atomicAdd(&g_cursor[d], 1);
        g_esrc[pos] = src[e];
    }
}

// ---------------- gather: warp per dst node, pull-mode, no atomics -----------
// aggout[n] = in_norm[n] * sum_{e in CSR[n]} h[src_e] * out_norm[src_e]
__global__ void __launch_bounds__(256)
gather_kernel(const float* __restrict__ h, float* __restrict__ aggout, int n) {
    int gw = (blockIdx.x * blockDim.x + threadIdx.x) >> 5;
    int lane = threadIdx.x & 31;
    if (gw >= n) return;
    int e0 = g_rowoff[gw];
    int e1 = g_rowoff[gw + 1];
    const float4* __restrict__ h4 = (const float4*)h;
    float4 acc = make_float4(0.f, 0.f, 0.f, 0.f);
    int e = e0;
    for (; e + 1 < e1; e += 2) {
        int s0 = g_esrc[e];
        int s1 = g_esrc[e + 1];
        float w0 = g_onorm[s0];
        float w1 = g_onorm[s1];
        float4 v0 = h4[s0 * 32 + lane];
        float4 v1 = h4[s1 * 32 + lane];
        acc.x = fmaf(v0.x, w0, acc.x); acc.y = fmaf(v0.y, w0, acc.y);
        acc.z = fmaf(v0.z, w0, acc.z); acc.w = fmaf(v0.w, w0, acc.w);
        acc.x = fmaf(v1.x, w1, acc.x); acc.y = fmaf(v1.y, w1, acc.y);
        acc.z = fmaf(v1.z, w1, acc.z); acc.w = fmaf(v1.w, w1, acc.w);
    }
    if (e < e1) {
        int s0 = g_esrc[e];
        float w0 = g_onorm[s0];
        float4 v0 = h4[s0 * 32 + lane];
        acc.x = fmaf(v0.x, w0, acc.x); acc.y = fmaf(v0.y, w0, acc.y);
        acc.z = fmaf(v0.z, w0, acc.z); acc.w = fmaf(v0.w, w0, acc.w);
    }
    float inn = g_inorm[gw];
    float4 r = make_float4(acc.x * inn, acc.y * inn, acc.z * inn, acc.w * inn);
    ((float4*)aggout)[gw * 32 + lane] = r;
}

// ---------------- GEMM: C[M,128] = A[M,128] @ W[128,128] + b (opt relu) ------
// block: 256 threads (16x16), tile 128x128, micro 8x8, K-tiles of 16
__global__ void __launch_bounds__(256)
gemm128_kernel(const float* __restrict__ A, const float* __restrict__ W,
               const float* __restrict__ bias, float* __restrict__ C,
               int M, int relu) {
    __shared__ float As[16][132];   // [k][row]  (transposed)
    __shared__ float Ws[16][132];   // [k][col]
    const int tid = threadIdx.x;
    const int tx = tid & 15;
    const int ty = tid >> 4;
    const int rowBase = blockIdx.x << 7;

    float acc[8][8];
    #pragma unroll
    for (int i = 0; i < 8; i++)
        #pragma unroll
        for (int j = 0; j < 8; j++) acc[i][j] = 0.f;

    for (int k0 = 0; k0 < 128; k0 += 16) {
        // A tile: 128 rows x 16 k, transposed into As[k][row]
        #pragma unroll
        for (int i = 0; i < 2; i++) {
            int idx = tid * 2 + i;          // 0..511
            int r = idx >> 2;               // row 0..127
            int c = idx & 3;                // which float4 of the 16-k strip
            int row = rowBase + r;
            float4 v = make_float4(0.f, 0.f, 0.f, 0.f);
            if (row < M) v = *(const float4*)(A + row * 128 + k0 + c * 4);
            As[c * 4 + 0][r] = v.x;
            As[c * 4 + 1][r] = v.y;
            As[c * 4 + 2][r] = v.z;
            As[c * 4 + 3][r] = v.w;
        }
        // W tile: 16 k x 128 cols
        #pragma unroll
        for (int i = 0; i < 2; i++) {
            int idx = tid * 2 + i;          // 0..511
            int kk = idx >> 5;              // 0..15
            int cc = idx & 31;              // float4 index in 128 cols
            float4 w = *(const float4*)(W + (k0 + kk) * 128 + cc * 4);
            *(float4*)(&Ws[kk][cc * 4]) = w;
        }
        __syncthreads();

        #pragma unroll
        for (int k = 0; k < 16; k++) {
            float4 a0 = *(const float4*)&As[k][ty * 8];
            float4 a1 = *(const float4*)&As[k][ty * 8 + 4];
            float4 w0 = *(const float4*)&Ws[k][tx * 8];
            float4 w1 = *(const float4*)&Ws[k][tx * 8 + 4];
            float a[8] = {a0.x, a0.y, a0.z, a0.w, a1.x, a1.y, a1.z, a1.w};
            float w[8] = {w0.x, w0.y, w0.z, w0.w, w1.x, w1.y, w1.z, w1.w};
            #pragma unroll
            for (int i = 0; i < 8; i++)
                #pragma unroll
                for (int j = 0; j < 8; j++)
                    acc[i][j] = fmaf(a[i], w[j], acc[i][j]);
        }
        __syncthreads();
    }

    float bv[8];
    #pragma unroll
    for (int j = 0; j < 8; j++) bv[j] = bias[tx * 8 + j];

    #pragma unroll
    for (int i = 0; i < 8; i++) {
        int row = rowBase + ty * 8 + i;
        if (row < M) {
            float o[8];
            #pragma unroll
            for (int j = 0; j < 8; j++) {
                float v = acc[i][j] + bv[j];
                if (relu) v = fmaxf(v, 0.f);
                o[j] = v;
            }
            *(float4*)(C + row * 128 + tx * 8)     = make_float4(o[0], o[1], o[2], o[3]);
            *(float4*)(C + row * 128 + tx * 8 + 4) = make_float4(o[4], o[5], o[6], o[7]);
        }
    }
}

// ---------------- classifier: out[M,40] = A[M,128] @ Wc[128,40] + bc ---------
// warp handles 4 rows; Wc in smem; A row elements broadcast via shfl
__global__ void __launch_bounds__(256)
classifier_kernel(const float* __restrict__ A, const float* __restrict__ Wc,
                  const float* __restrict__ bc, float* __restrict__ out, int M) {
    __shared__ float Ws[128 * 40];
    __shared__ float bs[40];
    for (int i = threadIdx.x; i < 128 * 40; i += 256) Ws[i] = Wc[i];
    if (threadIdx.x < 40) bs[threadIdx.x] = bc[threadIdx.x];
    __syncthreads();

    int lane = threadIdx.x & 31;
    int warp = (blockIdx.x * 256 + threadIdx.x) >> 5;
    int row0 = warp * 4;
    if (row0 >= M) return;

    float4 av[4];
    #pragma unroll
    for (int r = 0; r < 4; r++) {
        int row = row0 + r;
        av[r] = (row < M) ? ((const float4*)A)[row * 32 + lane]
                          : make_float4(0.f, 0.f, 0.f, 0.f);
    }

    float acc0[4] = {0.f, 0.f, 0.f, 0.f};
    float acc1[4] = {0.f, 0.f, 0.f, 0.f};
    bool hi = lane < 8;

    for (int k4 = 0; k4 < 32; k4++) {
        #pragma unroll
        for (int c = 0; c < 4; c++) {
            int k = k4 * 4 + c;
            float w0 = Ws[k * 40 + lane];
            float w1 = hi ? Ws[k * 40 + 32 + lane] : 0.f;
            #pragma unroll
            for (int r = 0; r < 4; r++) {
                float comp = (c == 0) ? av[r].x : (c == 1) ? av[r].y
                           : (c == 2) ? av[r].z : av[r].w;
                float aval = __shfl_sync(0xffffffffu, comp, k4);
                acc0[r] = fmaf(aval, w0, acc0[r]);
                acc1[r] = fmaf(aval, w1, acc1[r]);
            }
        }
    }

    #pragma unroll
    for (int r = 0; r < 4; r++) {
        int row = row0 + r;
        if (row < M) {
            out[row * 40 + lane] = acc0[r] + bs[lane];
            if (hi) out[row * 40 + 32 + lane] = acc1[r] + bs[32 + lane];
        }
    }
}

// ---------------- launch ------------------------------------------------------
extern "C" void kernel_launch(void* const* d_in, const int* in_sizes, int n_in,
                              void* d_out, int out_size) {
    const float* x   = (const float*)d_in[0];
    const int*   src = (const int*)  d_in[1];
    const int*   dst = (const int*)  d_in[2];
    const float* W1  = (const float*)d_in[3];
    const float* b1  = (const float*)d_in[4];
    const float* W2  = (const float*)d_in[5];
    const float* b2  = (const float*)d_in[6];
    const float* Wg  = (const float*)d_in[7];   // [3,128,128]
    const float* bg  = (const float*)d_in[8];   // [3,128]
    const float* Wc  = (const float*)d_in[9];
    const float* bc  = (const float*)d_in[10];
    float* out = (float*)d_out;

    const int N = in_sizes[0] / HID;
    const int E = in_sizes[1];

    float *h1, *h2, *agg;
    cudaGetSymbolAddress((void**)&h1,  g_h1);
    cudaGetSymbolAddress((void**)&h2,  g_h2);
    cudaGetSymbolAddress((void**)&agg, g_agg);

    const int TB = 256;
    const int gN = (N + TB - 1) / TB;
    const int gE = (E + TB - 1) / TB;
    const int nb = (N + 1023) / 1024;
    const int gGemm = (N + 127) / 128;
    const int gGather = (N + 7) / 8;          // 8 warps / block
    const int gCls = (N + 31) / 32;           // 8 warps x 4 rows / block

    // --- graph structure prep (every call; deterministic up to atomic order) ---
    zero_ints_kernel<<<gN, TB>>>(N);
    degree_kernel<<<gE, TB>>>(src, dst, E);
    norm_kernel<<<gN, TB>>>(N);
    scan1_kernel<<<nb, 1024>>>(N);
    scan2_kernel<<<1, 32>>>(nb, N, E);
    scan3_kernel<<<nb, 1024>>>(N);
    fill_kernel<<<gE, TB>>>(src, dst, E);

    // --- MLP front ---
    gemm128_kernel<<<gGemm, TB>>>(x,  W1, b1, h1, N, 0);
    gemm128_kernel<<<gGemm, TB>>>(h1, W2, b2, h2, N, 0);

    // --- 3 x (GraphConv + ReLU) ---
    gather_kernel<<<gGather, TB>>>(h2, agg, N);
    gemm128_kernel<<<gGemm, TB>>>(agg, Wg + 0 * 128 * 128, bg + 0 * 128, h1, N, 1);

    gather_kernel<<<gGather, TB>>>(h1, agg, N);
    gemm128_kernel<<<gGemm, TB>>>(agg, Wg + 1 * 128 * 128, bg + 1 * 128, h2, N, 1);

    gather_kernel<<<gGather, TB>>>(h2, agg, N);
    gemm128_kernel<<<gGemm, TB>>>(agg, Wg + 2 * 128 * 128, bg + 2 * 128, h1, N, 1);

    // --- classifier ---
    classifier_kernel<<<gCls, TB>>>(h1, Wc, bc, out, N);
}